// round 9
// baseline (speedup 1.0000x reference)
#include <cuda_runtime.h>
#include <cuda_fp16.h>

#define N_NODES 50000
#define N_EDGES 1600000
#define IN_C    128
#define HEADS   4
#define OUT_C   16
#define HC      64   // HEADS*OUT_C
#define NSPLIT  4    // parity-split fp16 accumulator buffers

// ---------------- scratch (static device globals; no allocs allowed) --------
__device__ __align__(16) __half g_xwh[N_NODES * HC];       // projected, fp16
__device__ __align__(16) float  g_asrc[N_NODES * HEADS];
__device__ __align__(16) float  g_adst[N_NODES * HEADS];
__device__ __align__(16) float  g_denom[N_NODES * HEADS];  // fp32 (exact norm)
__device__ __align__(16) __half g_aggh[NSPLIT * N_NODES * HC]; // fp16 split acc

__device__ __forceinline__ void red_add_f32(float* addr, float v) {
    asm volatile("red.global.add.f32 [%0], %1;" :: "l"(addr), "f"(v) : "memory");
}
// 8-half vectorized reduction (sm_90+)
__device__ __forceinline__ void red_add_v4h2(__half* addr, unsigned r0,
                                             unsigned r1, unsigned r2,
                                             unsigned r3) {
    asm volatile("red.global.add.noftz.v4.f16x2 [%0], {%1, %2, %3, %4};"
                 :: "l"(addr), "r"(r0), "r"(r1), "r"(r2), "r"(r3)
                 : "memory");
}

// ---------------- K0: zero accumulators -------------------------------------
__global__ void k_init(int n) {
    int t = blockIdx.x * blockDim.x + threadIdx.x;
    if (t < NSPLIT * n * HC / 8)   // 8 halves = 16B per thread
        *(uint4*)&g_aggh[(size_t)t * 8] = make_uint4(0u, 0u, 0u, 0u);
    if (t < n * HEADS) g_denom[t] = 0.f;
}

// ---------------- K1: xw = x @ W -> fp16, fused attention logits ------------
__global__ void k_proj(const float* __restrict__ x, const float* __restrict__ W,
                       const float* __restrict__ att_src,
                       const float* __restrict__ att_dst, int n) {
    extern __shared__ float smem[];
    float* sW = smem;
    float* sx = smem + IN_C * HC;
    int tid = threadIdx.x;
    int row0 = blockIdx.x * 64;

    for (int i = tid; i < IN_C * HC / 4; i += 256)
        ((float4*)sW)[i] = ((const float4*)W)[i];
    for (int i = tid; i < 64 * IN_C / 4; i += 256) {
        int r = i >> 5;
        float4 v = make_float4(0.f, 0.f, 0.f, 0.f);
        if (row0 + r < n) v = ((const float4*)x)[(size_t)(row0 + r) * 32 + (i & 31)];
        ((float4*)sx)[i] = v;
    }
    __syncthreads();

    int rg = tid >> 4;
    int c4 = (tid & 15) * 4;
    unsigned long long a0[4], a1[4];
#pragma unroll
    for (int i = 0; i < 4; i++) { a0[i] = 0ull; a1[i] = 0ull; }

#pragma unroll 4
    for (int k = 0; k < IN_C; k++) {
        float4 w = *(const float4*)&sW[k * HC + c4];
        unsigned long long w01, w23;
        asm("mov.b64 %0, {%1, %2};" : "=l"(w01) : "f"(w.x), "f"(w.y));
        asm("mov.b64 %0, {%1, %2};" : "=l"(w23) : "f"(w.z), "f"(w.w));
#pragma unroll
        for (int i = 0; i < 4; i++) {
            float xv = sx[(rg * 4 + i) * IN_C + k];
            unsigned long long xp;
            asm("mov.b64 %0, {%1, %1};" : "=l"(xp) : "f"(xv));
            asm("fma.rn.f32x2 %0, %1, %2, %0;" : "+l"(a0[i]) : "l"(xp), "l"(w01));
            asm("fma.rn.f32x2 %0, %1, %2, %0;" : "+l"(a1[i]) : "l"(xp), "l"(w23));
        }
    }

    float4 as = *(const float4*)(att_src + c4);
    float4 ad = *(const float4*)(att_dst + c4);
    int h = (tid & 15) >> 2;

#pragma unroll
    for (int i = 0; i < 4; i++) {
        int row = row0 + rg * 4 + i;
        float4 o;
        asm("mov.b64 {%0, %1}, %2;" : "=f"(o.x), "=f"(o.y) : "l"(a0[i]));
        asm("mov.b64 {%0, %1}, %2;" : "=f"(o.z), "=f"(o.w) : "l"(a1[i]));
        if (row < n) {
            __half2 p0 = __floats2half2_rn(o.x, o.y);
            __half2 p1 = __floats2half2_rn(o.z, o.w);
            uint2 u;
            u.x = *(unsigned*)&p0;
            u.y = *(unsigned*)&p1;
            *(uint2*)&g_xwh[row * HC + c4] = u;
        }
        float ss = o.x * as.x + o.y * as.y + o.z * as.z + o.w * as.w;
        float sd = o.x * ad.x + o.y * ad.y + o.z * ad.z + o.w * ad.w;
        ss += __shfl_down_sync(0xffffffffu, ss, 2);
        ss += __shfl_down_sync(0xffffffffu, ss, 1);
        sd += __shfl_down_sync(0xffffffffu, sd, 2);
        sd += __shfl_down_sync(0xffffffffu, sd, 1);
        if ((tid & 3) == 0 && row < n) {
            g_asrc[row * 4 + h] = ss;
            g_adst[row * 4 + h] = sd;
        }
    }
}

// ---------------- K2: fused edge pass — 2 edges/thread, 8 lanes/edge --------
// Thread q (0..7): head h=q>>1, channels [8q,8q+8). Edges 2p and 2p+1 are two
// fully independent chains (ILP) landing in different parity buffers
// (accumulation-error halving). No cross-lane dependencies (R7 lesson).
__global__ void k_edge(const int* __restrict__ ei, int e) {
    int gid = blockIdx.x * blockDim.x + threadIdx.x;
    int pair = gid >> 3;
    int e0 = pair * 2;
    if (e0 >= e) return;
    int q = gid & 7;
    int h = q >> 1;
    bool has1 = (e0 + 1) < e;

    int2 ss = *(const int2*)(ei + e0);        // src of e0, e0+1 (8B aligned)
    int2 dd = *(const int2*)(ei + e + e0);    // dst of e0, e0+1 (e is even)

    // edge 0
    float a0 = g_asrc[ss.x * 4 + h] + g_adst[dd.x * 4 + h];
    a0 = a0 > 0.f ? a0 : 0.2f * a0;
    float ex0 = __expf(a0);
    uint4 u0 = *(const uint4*)&g_xwh[ss.x * HC + q * 8];
    // edge 1 (independent chain)
    int s1 = has1 ? ss.y : ss.x;
    int d1 = has1 ? dd.y : dd.x;
    float a1 = g_asrc[s1 * 4 + h] + g_adst[d1 * 4 + h];
    a1 = a1 > 0.f ? a1 : 0.2f * a1;
    float ex1 = __expf(a1);
    uint4 u1 = *(const uint4*)&g_xwh[s1 * HC + q * 8];

    __half2 eh0 = __float2half2_rn(ex0);
    __half2 m00 = __hmul2(*(__half2*)&u0.x, eh0);
    __half2 m01 = __hmul2(*(__half2*)&u0.y, eh0);
    __half2 m02 = __hmul2(*(__half2*)&u0.z, eh0);
    __half2 m03 = __hmul2(*(__half2*)&u0.w, eh0);
    int b0 = e0 & 3;
    red_add_v4h2(g_aggh + (size_t)b0 * N_NODES * HC + dd.x * HC + q * 8,
                 *(unsigned*)&m00, *(unsigned*)&m01,
                 *(unsigned*)&m02, *(unsigned*)&m03);
    if ((q & 1) == 0) red_add_f32(g_denom + dd.x * 4 + h, ex0);

    if (has1) {
        __half2 eh1 = __float2half2_rn(ex1);
        __half2 m10 = __hmul2(*(__half2*)&u1.x, eh1);
        __half2 m11 = __hmul2(*(__half2*)&u1.y, eh1);
        __half2 m12 = __hmul2(*(__half2*)&u1.z, eh1);
        __half2 m13 = __hmul2(*(__half2*)&u1.w, eh1);
        int b1 = (e0 + 1) & 3;
        red_add_v4h2(g_aggh + (size_t)b1 * N_NODES * HC + d1 * HC + q * 8,
                     *(unsigned*)&m10, *(unsigned*)&m11,
                     *(unsigned*)&m12, *(unsigned*)&m13);
        if ((q & 1) == 0) red_add_f32(g_denom + d1 * 4 + h, ex1);
    }
}

// ---------------- K3: combine splits + normalize + ELU + out proj -----------
__global__ void k_out(const float* __restrict__ bias,
                      const float* __restrict__ W_out,
                      const float* __restrict__ b_out,
                      float* __restrict__ y, int n) {
    int gid = blockIdx.x * blockDim.x + threadIdx.x;
    int node = gid >> 4;
    int q = gid & 15;
    bool valid = node < n;
    int nc = valid ? node : 0;

    float dn  = g_denom[nc * 4 + (q >> 2)];
    float inv = 1.f / (dn + 1e-16f);
    size_t base = (size_t)nc * HC + q * 4;
    float4 a = make_float4(0.f, 0.f, 0.f, 0.f);
#pragma unroll
    for (int b = 0; b < NSPLIT; b++) {
        uint2 u = *(const uint2*)&g_aggh[(size_t)b * N_NODES * HC + base];
        float2 f0 = __half22float2(*(__half2*)&u.x);
        float2 f1 = __half22float2(*(__half2*)&u.y);
        a.x += f0.x; a.y += f0.y; a.z += f1.x; a.w += f1.y;
    }
    float4 b4 = *(const float4*)(bias + q * 4);
    float4 w  = *(const float4*)(W_out + q * 4);
    a.x = a.x * inv + b4.x; a.y = a.y * inv + b4.y;
    a.z = a.z * inv + b4.z; a.w = a.w * inv + b4.w;
    a.x = a.x > 0.f ? a.x : __expf(a.x) - 1.f;
    a.y = a.y > 0.f ? a.y : __expf(a.y) - 1.f;
    a.z = a.z > 0.f ? a.z : __expf(a.z) - 1.f;
    a.w = a.w > 0.f ? a.w : __expf(a.w) - 1.f;
    float p = a.x * w.x + a.y * w.y + a.z * w.z + a.w * w.w;
    p += __shfl_down_sync(0xffffffffu, p, 8, 16);
    p += __shfl_down_sync(0xffffffffu, p, 4, 16);
    p += __shfl_down_sync(0xffffffffu, p, 2, 16);
    p += __shfl_down_sync(0xffffffffu, p, 1, 16);
    if (valid && q == 0) y[node] = p + b_out[0];
}

// ---------------- launch -----------------------------------------------------
extern "C" void kernel_launch(void* const* d_in, const int* in_sizes, int n_in,
                              void* d_out, int out_size) {
    const float* x       = (const float*)d_in[0];
    const int*   ei      = (const int*)d_in[1];
    const float* W       = (const float*)d_in[2];
    const float* att_src = (const float*)d_in[3];
    const float* att_dst = (const float*)d_in[4];
    const float* bias    = (const float*)d_in[5];
    const float* W_out   = (const float*)d_in[6];
    const float* b_out   = (const float*)d_in[7];
    float*       y       = (float*)d_out;

    int n = in_sizes[0] / IN_C;   // 50000
    int e = in_sizes[1] / 2;      // 1600000

    const int B = 256;
    const int proj_smem = (IN_C * HC + 64 * IN_C) * (int)sizeof(float); // 64KB
    cudaFuncSetAttribute(k_proj, cudaFuncAttributeMaxDynamicSharedMemorySize,
                         proj_smem);

    int init_span = NSPLIT * n * HC / 8;
    k_init<<<(init_span + B - 1) / B, B>>>(n);
    k_proj<<<(n + 63) / 64, 256, proj_smem>>>(x, W, att_src, att_dst, n);
    int pairs = (e + 1) / 2;
    k_edge<<<((size_t)pairs * 8 + B - 1) / B, B>>>(ei, e);
    k_out<<<(n * 16 + B - 1) / B, B>>>(bias, W_out, b_out, y, n);
}